// round 12
// baseline (speedup 1.0000x reference)
#include <cuda_runtime.h>
#include <cuda_fp16.h>
#include <mma.h>

using namespace nvcuda;

// GPTQ int4 dequant + GEMM: wmma + split-K with fused last-CTA reduction.
// Inputs fp16-valued f32 (harness upcasts): x:[M,K], scales:[G,N], bias:[N],
// out:[M,N] f32; qweight:[K/8,N] i32, qzeros:[G,N/8] i32, g_idx:[K] i32.
//
// k0: convert x -> fp16 scratch (ILP=4)
// k1: (128 Ntiles x 8 Ksplits) CTAs; M64xN64 tile, K chunk 64, double-buffered
//     SMEM, one barrier per chunk. Dequant bit-trick: nib|0x6400 ==
//     half(1024+nib); hsub2(1024+z), one hmul2 round == ref's fp16 W.
//     Epilogue: store fp32 partial, threadfence + atomicInc; the 8th CTA per
//     n-tile reduces all partials in fixed split order (deterministic), applies
//     fp16 roundings + bias, writes out. Counter self-resets (graph-safe).

#define THREADS 256
#define BK 64
#define BN 64
#define SPLIT 8
#define MAX_M 64

__device__ __half g_xh[MAX_M * 8192];            // 1 MB fp16 x
__device__ float  g_part[SPLIT][MAX_M * 8192];   // fp32 partials
__device__ unsigned g_cnt[256];                  // per-n-tile retire counters (0-init)

__global__ void convert_x_kernel(const float* __restrict__ x, int n) {
    int i = (blockIdx.x * blockDim.x + threadIdx.x) * 16;
    if (i >= n) return;
#pragma unroll
    for (int u = 0; u < 4; ++u) {
        float4 v = *reinterpret_cast<const float4*>(x + i + u * 4);
        __half2 lo = __floats2half2_rn(v.x, v.y);
        __half2 hi = __floats2half2_rn(v.z, v.w);
        *reinterpret_cast<__half2*>(g_xh + i + u * 4)     = lo;
        *reinterpret_cast<__half2*>(g_xh + i + u * 4 + 2) = hi;
    }
}

__device__ __forceinline__ unsigned dq_pair(unsigned p, __half2 hz2, __half2 hs2) {
    p |= 0x64006400u;  // two halves: 1024 + nibble (exact)
    __half2 v = __hmul2(__hsub2(*reinterpret_cast<__half2*>(&p), hz2), hs2);
    return *reinterpret_cast<unsigned*>(&v);
}

__global__ __launch_bounds__(THREADS) void gptq_wmma_kernel(
    const int* __restrict__ qweight, const int* __restrict__ qzeros,
    const float* __restrict__ scales, const int* __restrict__ g_idx,
    const float* __restrict__ bias, float* __restrict__ out,
    int M, int K, int N)
{
    __shared__ __align__(16) __half A[2][64][72];
    __shared__ __align__(16) __half B[2][64][72];

    const int tid  = threadIdx.x;
    const int n0   = blockIdx.x * BN;
    const int spl  = blockIdx.y;
    const int Kper = K / SPLIT;
    const int kbeg = spl * Kper;
    const int kend = kbeg + Kper;

    // dequant mapping: thread owns column bn, qweight rows kq and kq+4
    const int bn   = tid & 63;
    const int kq   = tid >> 6;  // 0..3
    const int gn   = n0 + bn;
    const int zcol = gn >> 3;
    const int zsh  = (gn & 7) * 4;
    const int Nz   = N >> 3;

    // warp tiling: 8 warps -> (4 m16) x (2 n32)
    const int wid = tid >> 5;
    const int mr  = wid & 3;
    const int ng  = wid >> 2;

    uint4    aReg[2];
    unsigned qReg[2];
    __half2  hz2 = __half2half2(__ushort_as_half(0x6400));
    __half2  hs2 = __half2half2(__ushort_as_half(0));

    auto load_chunk = [&](int k0) {
#pragma unroll
        for (int u = 0; u < 2; ++u) {
            const int i = tid + u * THREADS;  // 0..511
            const int row = i >> 3, seg = i & 7;
            if (row < M)
                aReg[u] = *reinterpret_cast<const uint4*>(
                    g_xh + (size_t)row * K + k0 + seg * 8);
            else
                aReg[u] = make_uint4(0u, 0u, 0u, 0u);
        }
        const int krow = k0 >> 3;
        qReg[0] = (unsigned)qweight[(size_t)(krow + kq) * N + gn];
        qReg[1] = (unsigned)qweight[(size_t)(krow + kq + 4) * N + gn];
        const int g = g_idx[k0];  // uniform across 64-chunk (groupsize 128)
        const unsigned zq = (unsigned)qzeros[(size_t)g * Nz + zcol];
        const int z = (int)((zq >> zsh) & 15u) + 1;
        hz2 = __half2half2(__ushort_as_half((unsigned short)(0x6400 + z)));
        hs2 = __half2half2(__float2half_rn(scales[(size_t)g * N + gn]));
    };

    auto stage = [&](int buf) {
#pragma unroll
        for (int u = 0; u < 2; ++u) {
            const int i = tid + u * THREADS;
            const int row = i >> 3, seg = i & 7;
            *reinterpret_cast<uint4*>(&A[buf][row][seg * 8]) = aReg[u];
        }
#pragma unroll
        for (int u = 0; u < 2; ++u) {
            const unsigned q = qReg[u];
            uint4 v;
            v.x = dq_pair((q & 0xFu)         | ((q & 0xF0u) << 12),         hz2, hs2);
            v.y = dq_pair(((q >> 8) & 0xFu)  | (((q >> 8) & 0xF0u) << 12),  hz2, hs2);
            v.z = dq_pair(((q >> 16) & 0xFu) | (((q >> 16) & 0xF0u) << 12), hz2, hs2);
            v.w = dq_pair(((q >> 24) & 0xFu) | (((q >> 24) & 0xF0u) << 12), hz2, hs2);
            *reinterpret_cast<uint4*>(&B[buf][bn][(kq + u * 4) * 8]) = v;
        }
    };

    wmma::fragment<wmma::accumulator, 16, 16, 16, float> c[2];
    wmma::fill_fragment(c[0], 0.f);
    wmma::fill_fragment(c[1], 0.f);

    load_chunk(kbeg);
    int buf = 0;
    for (int k0 = kbeg; k0 < kend; k0 += BK) {
        stage(buf);
        __syncthreads();
        if (k0 + BK < kend) load_chunk(k0 + BK);  // overlaps mma below
#pragma unroll
        for (int ks = 0; ks < BK / 16; ++ks) {
            wmma::fragment<wmma::matrix_a, 16, 16, 16, __half, wmma::row_major> a;
            wmma::load_matrix_sync(a, &A[buf][mr * 16][ks * 16], 72);
#pragma unroll
            for (int t = 0; t < 2; ++t) {
                wmma::fragment<wmma::matrix_b, 16, 16, 16, __half, wmma::col_major> b;
                wmma::load_matrix_sync(b, &B[buf][(ng * 2 + t) * 16][ks * 16], 72);
                wmma::mma_sync(c[t], a, b, c[t]);
            }
        }
        buf ^= 1;
        // single barrier per chunk: stage(i+1) writes buf^1, whose last readers
        // (mma at i-1) are ordered by the barrier at iter i.
    }

    // ---- store fp32 partial tile
    float* dst = g_part[spl];
#pragma unroll
    for (int t = 0; t < 2; ++t)
        wmma::store_matrix_sync(
            dst + (size_t)(mr * 16) * N + n0 + (ng * 2 + t) * 16,
            c[t], N, wmma::mem_row_major);

    // ---- last CTA per n-tile reduces (threadFenceReduction pattern)
    __shared__ bool isLast;
    __threadfence();
    __syncthreads();
    if (tid == 0) {
        // atomicInc wraps to 0 when old == SPLIT-1 -> counter self-resets
        unsigned old = atomicInc(&g_cnt[blockIdx.x], SPLIT - 1);
        isLast = (old == SPLIT - 1);
    }
    __syncthreads();

    if (isLast) {
        __threadfence();  // acquire: see all peers' partial stores
#pragma unroll
        for (int u = 0; u < 4; ++u) {
            const int i   = tid + u * THREADS;   // 0..1023 float4 slots
            const int row = i >> 4;              // 0..63
            const int nc4 = (i & 15) * 4;        // 0..60
            if (row >= M) continue;
            const size_t off = (size_t)row * N + n0 + nc4;
            float4 s = make_float4(0.f, 0.f, 0.f, 0.f);
#pragma unroll
            for (int p = 0; p < SPLIT; ++p) {
                float4 v = *reinterpret_cast<const float4*>(&g_part[p][off]);
                s.x += v.x; s.y += v.y; s.z += v.z; s.w += v.w;
            }
            float4 b = *reinterpret_cast<const float4*>(bias + n0 + nc4);
            float4 r;
            r.x = __half2float(__float2half_rn(__half2float(__float2half_rn(s.x)) + b.x));
            r.y = __half2float(__float2half_rn(__half2float(__float2half_rn(s.y)) + b.y));
            r.z = __half2float(__float2half_rn(__half2float(__float2half_rn(s.z)) + b.z));
            r.w = __half2float(__float2half_rn(__half2float(__float2half_rn(s.w)) + b.w));
            *reinterpret_cast<float4*>(out + off) = r;
        }
    }
}

extern "C" void kernel_launch(void* const* d_in, const int* in_sizes, int n_in,
                              void* d_out, int out_size) {
    const float* x       = (const float*)d_in[0];
    const int*   qweight = (const int*)d_in[1];
    const int*   qzeros  = (const int*)d_in[2];
    const float* scales  = (const float*)d_in[3];
    const int*   g_idx   = (const int*)d_in[4];
    const float* bias    = (const float*)d_in[5];
    float*       out     = (float*)d_out;

    const int K = in_sizes[4];      // g_idx length
    const int M = in_sizes[0] / K;  // 64
    const int N = in_sizes[5];      // 8192

    const int nx = M * K;
    convert_x_kernel<<<(nx / 16 + THREADS - 1) / THREADS, THREADS>>>(x, nx);

    dim3 grid(N / BN, SPLIT);
    gptq_wmma_kernel<<<grid, THREADS>>>(qweight, qzeros, scales, g_idx,
                                        bias, out, M, K, N);
}

// round 13
// speedup vs baseline: 1.0373x; 1.0373x over previous
#include <cuda_runtime.h>
#include <cuda_fp16.h>
#include <mma.h>

using namespace nvcuda;

// GPTQ int4 dequant + GEMM: wmma, split-K, fused last-CTA reduction.
// Round-12 change: BN=128 with m32n32 warp tiles (2x4 warps) to cut SMEM
// traffic/MAC by 33% (profile showed L1=64% saturated, alu 35% > tensor 24%).
// Inputs fp16-valued f32 (harness upcasts): x:[M,K], scales:[G,N], bias:[N],
// out:[M,N] f32; qweight:[K/8,N] i32, qzeros:[G,N/8] i32, g_idx:[K] i32.

#define THREADS 256
#define BK 64
#define BN 128
#define SPLIT 16
#define MAX_M 64
#define LDS_A 72   // padded strides (conflict-free: 4r mod 32 per 8-lane phase)
#define LDS_B 72

__device__ __half g_xh[MAX_M * 8192];            // 1 MB fp16 x
__device__ float  g_part[SPLIT][MAX_M * 8192];   // fp32 partials (32 MB)
__device__ unsigned g_cnt[64];                   // per-n-tile retire counters

__global__ void convert_x_kernel(const float* __restrict__ x, int n) {
    int i = (blockIdx.x * blockDim.x + threadIdx.x) * 16;
    if (i >= n) return;
#pragma unroll
    for (int u = 0; u < 4; ++u) {
        float4 v = *reinterpret_cast<const float4*>(x + i + u * 4);
        __half2 lo = __floats2half2_rn(v.x, v.y);
        __half2 hi = __floats2half2_rn(v.z, v.w);
        *reinterpret_cast<__half2*>(g_xh + i + u * 4)     = lo;
        *reinterpret_cast<__half2*>(g_xh + i + u * 4 + 2) = hi;
    }
}

__device__ __forceinline__ unsigned dq_pair(unsigned p, __half2 hz2, __half2 hs2) {
    p |= 0x64006400u;  // two halves: 1024 + nibble (exact)
    __half2 v = __hmul2(__hsub2(*reinterpret_cast<__half2*>(&p), hz2), hs2);
    return *reinterpret_cast<unsigned*>(&v);
}

__global__ __launch_bounds__(THREADS) void gptq_wmma_kernel(
    const int* __restrict__ qweight, const int* __restrict__ qzeros,
    const float* __restrict__ scales, const int* __restrict__ g_idx,
    const float* __restrict__ bias, float* __restrict__ out,
    int M, int K, int N)
{
    extern __shared__ __align__(16) __half sm[];
    // A: 2 bufs x 64 x LDS_A ; B: 2 bufs x 128 x LDS_B
    __half* Ab = sm;                       // [buf][row][col] row-major, ld 72
    __half* Bb = sm + 2 * 64 * LDS_A;      // [buf][n][k], ld 72

    const int tid  = threadIdx.x;
    const int n0   = blockIdx.x * BN;
    const int spl  = blockIdx.y;
    const int Kper = K / SPLIT;            // 512
    const int kbeg = spl * Kper;
    const int kend = kbeg + Kper;

    // dequant mapping: thread owns column bn; qweight krows kq+2u (u=0..3)
    const int bn   = tid & 127;
    const int kq   = tid >> 7;  // 0..1
    const int gn   = n0 + bn;
    const int zcol = gn >> 3;
    const int zsh  = (gn & 7) * 4;
    const int Nz   = N >> 3;

    // warp tiling: 8 warps -> (2 m32) x (4 n32); each warp m32 x n32
    const int wid = tid >> 5;
    const int mr  = wid & 1;
    const int ng  = wid >> 1;

    uint4    aReg[2];
    unsigned qReg[4];
    __half2  hz2 = __half2half2(__ushort_as_half(0x6400));
    __half2  hs2 = __half2half2(__ushort_as_half(0));

    auto load_chunk = [&](int k0) {
#pragma unroll
        for (int u = 0; u < 2; ++u) {
            const int i = tid + u * THREADS;  // 0..511
            const int row = i >> 3, seg = i & 7;
            if (row < M)
                aReg[u] = *reinterpret_cast<const uint4*>(
                    g_xh + (size_t)row * K + k0 + seg * 8);
            else
                aReg[u] = make_uint4(0u, 0u, 0u, 0u);
        }
        const int krow = k0 >> 3;
#pragma unroll
        for (int u = 0; u < 4; ++u)
            qReg[u] = (unsigned)qweight[(size_t)(krow + kq + 2 * u) * N + gn];
        const int g = g_idx[k0];  // uniform across 64-chunk (groupsize 128)
        const unsigned zq = (unsigned)qzeros[(size_t)g * Nz + zcol];
        const int z = (int)((zq >> zsh) & 15u) + 1;
        hz2 = __half2half2(__ushort_as_half((unsigned short)(0x6400 + z)));
        hs2 = __half2half2(__float2half_rn(scales[(size_t)g * N + gn]));
    };

    auto stage = [&](int buf) {
        __half* A = Ab + buf * 64 * LDS_A;
        __half* B = Bb + buf * 128 * LDS_B;
#pragma unroll
        for (int u = 0; u < 2; ++u) {
            const int i = tid + u * THREADS;
            const int row = i >> 3, seg = i & 7;
            *reinterpret_cast<uint4*>(A + row * LDS_A + seg * 8) = aReg[u];
        }
#pragma unroll
        for (int u = 0; u < 4; ++u) {
            const unsigned q = qReg[u];
            uint4 v;
            v.x = dq_pair((q & 0xFu)         | ((q & 0xF0u) << 12),         hz2, hs2);
            v.y = dq_pair(((q >> 8) & 0xFu)  | (((q >> 8) & 0xF0u) << 12),  hz2, hs2);
            v.z = dq_pair(((q >> 16) & 0xFu) | (((q >> 16) & 0xF0u) << 12), hz2, hs2);
            v.w = dq_pair(((q >> 24) & 0xFu) | (((q >> 24) & 0xF0u) << 12), hz2, hs2);
            *reinterpret_cast<uint4*>(B + bn * LDS_B + (kq + 2 * u) * 8) = v;
        }
    };

    wmma::fragment<wmma::accumulator, 16, 16, 16, float> c[2][2];
#pragma unroll
    for (int im = 0; im < 2; ++im)
#pragma unroll
        for (int in = 0; in < 2; ++in)
            wmma::fill_fragment(c[im][in], 0.f);

    load_chunk(kbeg);
    int buf = 0;
    for (int k0 = kbeg; k0 < kend; k0 += BK) {
        stage(buf);
        __syncthreads();
        if (k0 + BK < kend) load_chunk(k0 + BK);  // overlaps mma below
        const __half* A = Ab + buf * 64 * LDS_A;
        const __half* B = Bb + buf * 128 * LDS_B;
#pragma unroll
        for (int ks = 0; ks < BK / 16; ++ks) {
            wmma::fragment<wmma::matrix_a, 16, 16, 16, __half, wmma::row_major> a[2];
#pragma unroll
            for (int im = 0; im < 2; ++im)
                wmma::load_matrix_sync(
                    a[im], A + (mr * 32 + im * 16) * LDS_A + ks * 16, LDS_A);
#pragma unroll
            for (int in = 0; in < 2; ++in) {
                wmma::fragment<wmma::matrix_b, 16, 16, 16, __half, wmma::col_major> b;
                wmma::load_matrix_sync(
                    b, B + (ng * 32 + in * 16) * LDS_B + ks * 16, LDS_B);
#pragma unroll
                for (int im = 0; im < 2; ++im)
                    wmma::mma_sync(c[im][in], a[im], b, c[im][in]);
            }
        }
        buf ^= 1;
        // single barrier per chunk: stage(i+1) writes buf^1, whose last readers
        // (mma at i-1) are ordered by the barrier at iter i.
    }

    // ---- store fp32 partial tile
    float* dst = g_part[spl];
#pragma unroll
    for (int im = 0; im < 2; ++im)
#pragma unroll
        for (int in = 0; in < 2; ++in)
            wmma::store_matrix_sync(
                dst + (size_t)(mr * 32 + im * 16) * N + n0 + ng * 32 + in * 16,
                c[im][in], N, wmma::mem_row_major);

    // ---- last CTA per n-tile reduces (threadFenceReduction pattern)
    __shared__ bool isLast;
    __threadfence();
    __syncthreads();
    if (tid == 0) {
        unsigned old = atomicInc(&g_cnt[blockIdx.x], SPLIT - 1);  // self-resets
        isLast = (old == SPLIT - 1);
    }
    __syncthreads();

    if (isLast) {
        __threadfence();  // acquire: see all peers' partial stores
#pragma unroll
        for (int u = 0; u < 8; ++u) {
            const int i   = tid + u * THREADS;   // 0..2047 float4 slots
            const int row = i >> 5;              // 0..63 (32 float4 per row)
            const int nc4 = (i & 31) * 4;        // 0..124
            if (row >= M) continue;
            const size_t off = (size_t)row * N + n0 + nc4;
            float4 s = make_float4(0.f, 0.f, 0.f, 0.f);
#pragma unroll
            for (int p = 0; p < SPLIT; ++p) {
                float4 v = *reinterpret_cast<const float4*>(&g_part[p][off]);
                s.x += v.x; s.y += v.y; s.z += v.z; s.w += v.w;
            }
            float4 b = *reinterpret_cast<const float4*>(bias + n0 + nc4);
            float4 r;
            r.x = __half2float(__float2half_rn(__half2float(__float2half_rn(s.x)) + b.x));
            r.y = __half2float(__float2half_rn(__half2float(__float2half_rn(s.y)) + b.y));
            r.z = __half2float(__float2half_rn(__half2float(__float2half_rn(s.z)) + b.z));
            r.w = __half2float(__float2half_rn(__half2float(__float2half_rn(s.w)) + b.w));
            *reinterpret_cast<float4*>(out + off) = r;
        }
    }
}

extern "C" void kernel_launch(void* const* d_in, const int* in_sizes, int n_in,
                              void* d_out, int out_size) {
    const float* x       = (const float*)d_in[0];
    const int*   qweight = (const int*)d_in[1];
    const int*   qzeros  = (const int*)d_in[2];
    const float* scales  = (const float*)d_in[3];
    const int*   g_idx   = (const int*)d_in[4];
    const float* bias    = (const float*)d_in[5];
    float*       out     = (float*)d_out;

    const int K = in_sizes[4];      // g_idx length
    const int M = in_sizes[0] / K;  // 64
    const int N = in_sizes[5];      // 8192

    const int smem_bytes =
        (2 * 64 * LDS_A + 2 * BN * LDS_B) * (int)sizeof(__half);  // 55296
    cudaFuncSetAttribute(gptq_wmma_kernel,
                         cudaFuncAttributeMaxDynamicSharedMemorySize,
                         smem_bytes);

    const int nx = M * K;
    convert_x_kernel<<<(nx / 16 + THREADS - 1) / THREADS, THREADS>>>(x, nx);

    dim3 grid(N / BN, SPLIT);
    gptq_wmma_kernel<<<grid, THREADS, smem_bytes>>>(qweight, qzeros, scales,
                                                    g_idx, bias, out, M, K, N);
}

// round 14
// speedup vs baseline: 1.0379x; 1.0006x over previous
#include <cuda_runtime.h>
#include <cuda_fp16.h>
#include <mma.h>

using namespace nvcuda;

// GPTQ int4 dequant + GEMM: wmma, split-K, fused last-CTA reduction.
// Round-13 change: within-8 k-interleave [0,4,1,5,2,6,3,7] applied to BOTH
// A (free, in convert kernel) and B (dequant): nibble pair (s, s+4) extracts
// with ONE LOP3 ((q>>4s & 0x000F000F) | 0x64006400) into a ready half2,
// cutting dequant ALU ~35% (profile: alu 33% >= tensor 25% was the binder).
// GEMM is k-permutation invariant when A and B share the permutation.
// Inputs fp16-valued f32 (harness upcasts): x:[M,K], scales:[G,N], bias:[N],
// out:[M,N] f32; qweight:[K/8,N] i32, qzeros:[G,N/8] i32, g_idx:[K] i32.

#define THREADS 256
#define BK 64
#define BN 128
#define SPLIT 16
#define MAX_M 64
#define LDS_A 72
#define LDS_B 72

__device__ __half g_xh[MAX_M * 8192];            // 1 MB fp16 x (k-interleaved)
__device__ float  g_part[SPLIT][MAX_M * 8192];   // fp32 partials
__device__ unsigned g_cnt[64];                   // per-n-tile retire counters

// x scratch holds each 8-k block in order [0,4,1,5,2,6,3,7]
__global__ void convert_x_kernel(const float* __restrict__ x, int n) {
    int i = (blockIdx.x * blockDim.x + threadIdx.x) * 16;
    if (i >= n) return;
#pragma unroll
    for (int u = 0; u < 2; ++u) {  // two 8-blocks
        const int b = i + u * 8;
        float4 v0 = *reinterpret_cast<const float4*>(x + b);      // k 0-3
        float4 v1 = *reinterpret_cast<const float4*>(x + b + 4);  // k 4-7
        *reinterpret_cast<__half2*>(g_xh + b)     = __floats2half2_rn(v0.x, v1.x);
        *reinterpret_cast<__half2*>(g_xh + b + 2) = __floats2half2_rn(v0.y, v1.y);
        *reinterpret_cast<__half2*>(g_xh + b + 4) = __floats2half2_rn(v0.z, v1.z);
        *reinterpret_cast<__half2*>(g_xh + b + 6) = __floats2half2_rn(v0.w, v1.w);
    }
}

// one LOP3: nibbles (s, s+4) of q -> half2 {1024+n_s, 1024+n_{s+4}}, then
// exact hsub2 and one hmul2 round == ref's fp16 W
__device__ __forceinline__ unsigned dq_ilv(unsigned p, __half2 hz2, __half2 hs2) {
    unsigned t = (p & 0x000F000Fu) | 0x64006400u;
    __half2 v = __hmul2(__hsub2(*reinterpret_cast<__half2*>(&t), hz2), hs2);
    return *reinterpret_cast<unsigned*>(&v);
}

__global__ __launch_bounds__(THREADS) void gptq_wmma_kernel(
    const int* __restrict__ qweight, const int* __restrict__ qzeros,
    const float* __restrict__ scales, const int* __restrict__ g_idx,
    const float* __restrict__ bias, float* __restrict__ out,
    int M, int K, int N)
{
    extern __shared__ __align__(16) __half sm[];
    __half* Ab = sm;                       // [buf][row][col], ld 72
    __half* Bb = sm + 2 * 64 * LDS_A;      // [buf][n][k], ld 72

    const int tid  = threadIdx.x;
    const int n0   = blockIdx.x * BN;
    const int spl  = blockIdx.y;
    const int Kper = K / SPLIT;            // 512
    const int kbeg = spl * Kper;
    const int kend = kbeg + Kper;

    // dequant mapping: thread owns column bn; qweight krows kq+2u (u=0..3)
    const int bn   = tid & 127;
    const int kq   = tid >> 7;  // 0..1
    const int gn   = n0 + bn;
    const int zcol = gn >> 3;
    const int zsh  = (gn & 7) * 4;
    const int Nz   = N >> 3;

    // warp tiling: 8 warps -> (2 m32) x (4 n32)
    const int wid = tid >> 5;
    const int mr  = wid & 1;
    const int ng  = wid >> 1;

    uint4    aReg[2];
    unsigned qReg[4];
    __half2  hz2 = __half2half2(__ushort_as_half(0x6400));
    __half2  hs2 = __half2half2(__ushort_as_half(0));

    auto load_chunk = [&](int k0) {
#pragma unroll
        for (int u = 0; u < 2; ++u) {
            const int i = tid + u * THREADS;  // 0..511
            const int row = i >> 3, seg = i & 7;
            if (row < M)
                aReg[u] = *reinterpret_cast<const uint4*>(
                    g_xh + (size_t)row * K + k0 + seg * 8);
            else
                aReg[u] = make_uint4(0u, 0u, 0u, 0u);
        }
        const int krow = k0 >> 3;
#pragma unroll
        for (int u = 0; u < 4; ++u)
            qReg[u] = (unsigned)qweight[(size_t)(krow + kq + 2 * u) * N + gn];
        const int g = g_idx[k0];  // uniform across 64-chunk (groupsize 128)
        const unsigned zq = (unsigned)qzeros[(size_t)g * Nz + zcol];
        const int z = (int)((zq >> zsh) & 15u) + 1;
        hz2 = __half2half2(__ushort_as_half((unsigned short)(0x6400 + z)));
        hs2 = __half2half2(__float2half_rn(scales[(size_t)g * N + gn]));
    };

    auto stage = [&](int buf) {
        __half* A = Ab + buf * 64 * LDS_A;
        __half* B = Bb + buf * 128 * LDS_B;
#pragma unroll
        for (int u = 0; u < 2; ++u) {
            const int i = tid + u * THREADS;
            const int row = i >> 3, seg = i & 7;
            *reinterpret_cast<uint4*>(A + row * LDS_A + seg * 8) = aReg[u];
        }
#pragma unroll
        for (int u = 0; u < 4; ++u) {
            const unsigned q = qReg[u];
            // interleaved dequant: positions [0..7] hold k [0,4,1,5,2,6,3,7]
            uint4 v;
            v.x = dq_ilv(q,       hz2, hs2);
            v.y = dq_ilv(q >> 4,  hz2, hs2);
            v.z = dq_ilv(q >> 8,  hz2, hs2);
            v.w = dq_ilv(q >> 12, hz2, hs2);
            *reinterpret_cast<uint4*>(B + bn * LDS_B + (kq + 2 * u) * 8) = v;
        }
    };

    wmma::fragment<wmma::accumulator, 16, 16, 16, float> c[2][2];
#pragma unroll
    for (int im = 0; im < 2; ++im)
#pragma unroll
        for (int in = 0; in < 2; ++in)
            wmma::fill_fragment(c[im][in], 0.f);

    load_chunk(kbeg);
    int buf = 0;
    for (int k0 = kbeg; k0 < kend; k0 += BK) {
        stage(buf);
        __syncthreads();
        if (k0 + BK < kend) load_chunk(k0 + BK);  // overlaps mma below
        const __half* A = Ab + buf * 64 * LDS_A;
        const __half* B = Bb + buf * 128 * LDS_B;
#pragma unroll
        for (int ks = 0; ks < BK / 16; ++ks) {
            wmma::fragment<wmma::matrix_a, 16, 16, 16, __half, wmma::row_major> a[2];
#pragma unroll
            for (int im = 0; im < 2; ++im)
                wmma::load_matrix_sync(
                    a[im], A + (mr * 32 + im * 16) * LDS_A + ks * 16, LDS_A);
#pragma unroll
            for (int in = 0; in < 2; ++in) {
                wmma::fragment<wmma::matrix_b, 16, 16, 16, __half, wmma::col_major> b;
                wmma::load_matrix_sync(
                    b, B + (ng * 32 + in * 16) * LDS_B + ks * 16, LDS_B);
#pragma unroll
                for (int im = 0; im < 2; ++im)
                    wmma::mma_sync(c[im][in], a[im], b, c[im][in]);
            }
        }
        buf ^= 1;
        // single barrier per chunk: stage(i+1) writes buf^1, whose last readers
        // (mma at i-1) are ordered by the barrier at iter i.
    }

    // ---- store fp32 partial tile
    float* dst = g_part[spl];
#pragma unroll
    for (int im = 0; im < 2; ++im)
#pragma unroll
        for (int in = 0; in < 2; ++in)
            wmma::store_matrix_sync(
                dst + (size_t)(mr * 32 + im * 16) * N + n0 + ng * 32 + in * 16,
                c[im][in], N, wmma::mem_row_major);

    // ---- last CTA per n-tile reduces (threadFenceReduction pattern)
    __shared__ bool isLast;
    __threadfence();
    __syncthreads();
    if (tid == 0) {
        unsigned old = atomicInc(&g_cnt[blockIdx.x], SPLIT - 1);  // self-resets
        isLast = (old == SPLIT - 1);
    }
    __syncthreads();

    if (isLast) {
        __threadfence();  // acquire: see all peers' partial stores
#pragma unroll
        for (int u = 0; u < 8; ++u) {
            const int i   = tid + u * THREADS;   // 0..2047 float4 slots
            const int row = i >> 5;              // 0..63
            const int nc4 = (i & 31) * 4;        // 0..124
            if (row >= M) continue;
            const size_t off = (size_t)row * N + n0 + nc4;
            float4 s = make_float4(0.f, 0.f, 0.f, 0.f);
#pragma unroll
            for (int p = 0; p < SPLIT; ++p) {
                float4 v = *reinterpret_cast<const float4*>(&g_part[p][off]);
                s.x += v.x; s.y += v.y; s.z += v.z; s.w += v.w;
            }
            float4 b = *reinterpret_cast<const float4*>(bias + n0 + nc4);
            float4 r;
            r.x = __half2float(__float2half_rn(__half2float(__float2half_rn(s.x)) + b.x));
            r.y = __half2float(__float2half_rn(__half2float(__float2half_rn(s.y)) + b.y));
            r.z = __half2float(__float2half_rn(__half2float(__float2half_rn(s.z)) + b.z));
            r.w = __half2float(__float2half_rn(__half2float(__float2half_rn(s.w)) + b.w));
            *reinterpret_cast<float4*>(out + off) = r;
        }
    }
}

extern "C" void kernel_launch(void* const* d_in, const int* in_sizes, int n_in,
                              void* d_out, int out_size) {
    const float* x       = (const float*)d_in[0];
    const int*   qweight = (const int*)d_in[1];
    const int*   qzeros  = (const int*)d_in[2];
    const float* scales  = (const float*)d_in[3];
    const int*   g_idx   = (const int*)d_in[4];
    const float* bias    = (const float*)d_in[5];
    float*       out     = (float*)d_out;

    const int K = in_sizes[4];      // g_idx length
    const int M = in_sizes[0] / K;  // 64
    const int N = in_sizes[5];      // 8192

    const int smem_bytes =
        (2 * 64 * LDS_A + 2 * BN * LDS_B) * (int)sizeof(__half);  // 55296
    cudaFuncSetAttribute(gptq_wmma_kernel,
                         cudaFuncAttributeMaxDynamicSharedMemorySize,
                         smem_bytes);

    const int nx = M * K;
    convert_x_kernel<<<(nx / 16 + THREADS - 1) / THREADS, THREADS>>>(x, nx);

    dim3 grid(N / BN, SPLIT);
    gptq_wmma_kernel<<<grid, THREADS, smem_bytes>>>(qweight, qzeros, scales,
                                                    g_idx, bias, out, M, K, N);
}

// round 16
// speedup vs baseline: 1.0848x; 1.0452x over previous
#include <cuda_runtime.h>
#include <cuda_fp16.h>
#include <mma.h>

using namespace nvcuda;

// GPTQ int4 dequant + GEMM: wmma, split-K, fused last-CTA reduction.
// R15: occupancy push on the proven R13 base (tcgen05 unavailable: harness
// ptxas targets sm_103 non-a). cp.async A-staging (kills aReg + LDG->STS
// chain; 144B row stride = 16B-aligned, LDSM conflict-free) and
// __launch_bounds__(256,4) to lift regs-bound residency 3 -> 4 CTAs/SM.
// Inputs fp16-valued f32 (harness upcasts): x:[M,K], scales:[G,N], bias:[N],
// out:[M,N] f32; qweight:[K/8,N] i32, qzeros:[G,N/8] i32, g_idx:[K] i32.

#define THREADS 256
#define BK 64
#define BN 128
#define SPLIT 16
#define MAX_M 64
#define LDS_A 72   // 144B stride: 16x9 bytes -> cp.async-aligned + LDSM-clean
#define LDS_B 72

__device__ __half g_xh[MAX_M * 8192];            // 1 MB fp16 x (k-interleaved)
__device__ float  g_part[SPLIT][MAX_M * 8192];   // fp32 partials
__device__ unsigned g_cnt[64];                   // per-n-tile retire counters

// x scratch holds each 8-k block in order [0,4,1,5,2,6,3,7]
__global__ void convert_x_kernel(const float* __restrict__ x, int n) {
    int i = (blockIdx.x * blockDim.x + threadIdx.x) * 16;
    if (i >= n) return;
#pragma unroll
    for (int u = 0; u < 2; ++u) {  // two 8-blocks
        const int b = i + u * 8;
        float4 v0 = *reinterpret_cast<const float4*>(x + b);      // k 0-3
        float4 v1 = *reinterpret_cast<const float4*>(x + b + 4);  // k 4-7
        *reinterpret_cast<__half2*>(g_xh + b)     = __floats2half2_rn(v0.x, v1.x);
        *reinterpret_cast<__half2*>(g_xh + b + 2) = __floats2half2_rn(v0.y, v1.y);
        *reinterpret_cast<__half2*>(g_xh + b + 4) = __floats2half2_rn(v0.z, v1.z);
        *reinterpret_cast<__half2*>(g_xh + b + 6) = __floats2half2_rn(v0.w, v1.w);
    }
}

// one LOP3 pair-extract (k-interleaved); exact hsub2 + one hmul2 == ref fp16 W
__device__ __forceinline__ unsigned dq_ilv(unsigned p, __half2 hz2, __half2 hs2) {
    unsigned t = (p & 0x000F000Fu) | 0x64006400u;
    __half2 v = __hmul2(__hsub2(*reinterpret_cast<__half2*>(&t), hz2), hs2);
    return *reinterpret_cast<unsigned*>(&v);
}

__device__ __forceinline__ void cp_async16(void* smem_dst, const void* src) {
    unsigned s = (unsigned)__cvta_generic_to_shared(smem_dst);
    asm volatile("cp.async.cg.shared.global [%0], [%1], 16;\n"
                 :: "r"(s), "l"(src));
}

__global__ __launch_bounds__(THREADS, 4) void gptq_wmma_kernel(
    const int* __restrict__ qweight, const int* __restrict__ qzeros,
    const float* __restrict__ scales, const int* __restrict__ g_idx,
    const float* __restrict__ bias, float* __restrict__ out,
    int M, int K, int N)
{
    extern __shared__ __align__(16) __half sm[];
    __half* Ab = sm;                       // [buf][row][col], ld 72
    __half* Bb = sm + 2 * 64 * LDS_A;      // [buf][n][k], ld 72

    const int tid  = threadIdx.x;
    const int n0   = blockIdx.x * BN;
    const int spl  = blockIdx.y;
    const int Kper = K / SPLIT;            // 512
    const int kbeg = spl * Kper;
    const int kend = kbeg + Kper;

    // dequant mapping: thread owns column bn; qweight krows kq+2u (u=0..3)
    const int bn   = tid & 127;
    const int kq   = tid >> 7;  // 0..1
    const int gn   = n0 + bn;
    const int zcol = gn >> 3;
    const int zsh  = (gn & 7) * 4;
    const int Nz   = N >> 3;

    // warp tiling: 8 warps -> (2 m32) x (4 n32)
    const int wid = tid >> 5;
    const int mr  = wid & 1;
    const int ng  = wid >> 1;

    unsigned qReg[4];
    __half2  hz2 = __half2half2(__ushort_as_half(0x6400));
    __half2  hs2 = __half2half2(__ushort_as_half(0));

    // A: cp.async direct gmem(g_xh, L2-resident) -> SMEM; 512 x 16B segs
    auto issue_A = [&](int k0, int buf) {
        __half* A = Ab + buf * 64 * LDS_A;
#pragma unroll
        for (int u = 0; u < 2; ++u) {
            const int i = tid + u * THREADS;       // 0..511
            const int row = i >> 3, seg = i & 7;   // 64 rows x 8 segs
            if (row < M)
                cp_async16(A + row * LDS_A + seg * 8,
                           g_xh + (size_t)row * K + k0 + seg * 8);
        }
        asm volatile("cp.async.commit_group;\n");
    };

    auto load_q = [&](int k0) {
        const int krow = k0 >> 3;
#pragma unroll
        for (int u = 0; u < 4; ++u)
            qReg[u] = (unsigned)qweight[(size_t)(krow + kq + 2 * u) * N + gn];
        const int g = g_idx[k0];  // uniform across 64-chunk (groupsize 128)
        const unsigned zq = (unsigned)qzeros[(size_t)g * Nz + zcol];
        const int z = (int)((zq >> zsh) & 15u) + 1;
        hz2 = __half2half2(__ushort_as_half((unsigned short)(0x6400 + z)));
        hs2 = __half2half2(__float2half_rn(scales[(size_t)g * N + gn]));
    };

    auto stage_B = [&](int buf) {
        __half* B = Bb + buf * 128 * LDS_B;
#pragma unroll
        for (int u = 0; u < 4; ++u) {
            const unsigned q = qReg[u];
            // interleaved dequant: positions [0..7] hold k [0,4,1,5,2,6,3,7]
            uint4 v;
            v.x = dq_ilv(q,       hz2, hs2);
            v.y = dq_ilv(q >> 4,  hz2, hs2);
            v.z = dq_ilv(q >> 8,  hz2, hs2);
            v.w = dq_ilv(q >> 12, hz2, hs2);
            *reinterpret_cast<uint4*>(B + bn * LDS_B + (kq + 2 * u) * 8) = v;
        }
    };

    // zero A pad rows once (rows >= M are never written by cp.async)
    if (M < 64) {
        for (int i = tid; i < 2 * (64 - M) * 8; i += THREADS) {
            const int b = i / ((64 - M) * 8);
            const int r = M + (i / 8) % (64 - M);
            const int s = i & 7;
            *reinterpret_cast<uint4*>(Ab + b * 64 * LDS_A + r * LDS_A + s * 8) =
                make_uint4(0u, 0u, 0u, 0u);
        }
        __syncthreads();
    }

    wmma::fragment<wmma::accumulator, 16, 16, 16, float> c[2][2];
#pragma unroll
    for (int im = 0; im < 2; ++im)
#pragma unroll
        for (int in = 0; in < 2; ++in)
            wmma::fill_fragment(c[im][in], 0.f);

    issue_A(kbeg, 0);
    load_q(kbeg);
    int buf = 0;
    for (int k0 = kbeg; k0 < kend; k0 += BK) {
        stage_B(buf);
        asm volatile("cp.async.wait_group 0;\n" ::: "memory");
        __syncthreads();
        if (k0 + BK < kend) {
            issue_A(k0 + BK, buf ^ 1);  // buf^1 retired by barrier above
            load_q(k0 + BK);            // overlaps mma below
        }
        const __half* A = Ab + buf * 64 * LDS_A;
        const __half* B = Bb + buf * 128 * LDS_B;
#pragma unroll
        for (int ks = 0; ks < BK / 16; ++ks) {
            wmma::fragment<wmma::matrix_a, 16, 16, 16, __half, wmma::row_major> a[2];
#pragma unroll
            for (int im = 0; im < 2; ++im)
                wmma::load_matrix_sync(
                    a[im], A + (mr * 32 + im * 16) * LDS_A + ks * 16, LDS_A);
#pragma unroll
            for (int in = 0; in < 2; ++in) {
                wmma::fragment<wmma::matrix_b, 16, 16, 16, __half, wmma::col_major> b;
                wmma::load_matrix_sync(
                    b, B + (ng * 32 + in * 16) * LDS_B + ks * 16, LDS_B);
#pragma unroll
                for (int im = 0; im < 2; ++im)
                    wmma::mma_sync(c[im][in], a[im], b, c[im][in]);
            }
        }
        buf ^= 1;
        // single barrier per chunk: writes at iter i+1 target buf^1, whose last
        // readers (mma at i-1) are ordered by the barrier at iter i.
    }

    // ---- store fp32 partial tile
    float* dst = g_part[spl];
#pragma unroll
    for (int im = 0; im < 2; ++im)
#pragma unroll
        for (int in = 0; in < 2; ++in)
            wmma::store_matrix_sync(
                dst + (size_t)(mr * 32 + im * 16) * N + n0 + ng * 32 + in * 16,
                c[im][in], N, wmma::mem_row_major);

    // ---- last CTA per n-tile reduces (threadFenceReduction pattern)
    __shared__ bool isLast;
    __threadfence();
    __syncthreads();
    if (tid == 0) {
        unsigned old = atomicInc(&g_cnt[blockIdx.x], SPLIT - 1);  // self-resets
        isLast = (old == SPLIT - 1);
    }
    __syncthreads();

    if (isLast) {
        __threadfence();  // acquire: see all peers' partial stores
#pragma unroll
        for (int u = 0; u < 8; ++u) {
            const int i   = tid + u * THREADS;   // 0..2047 float4 slots
            const int row = i >> 5;              // 0..63
            const int nc4 = (i & 31) * 4;        // 0..124
            if (row >= M) continue;
            const size_t off = (size_t)row * N + n0 + nc4;
            float4 s = make_float4(0.f, 0.f, 0.f, 0.f);
#pragma unroll
            for (int p = 0; p < SPLIT; ++p) {
                float4 v = *reinterpret_cast<const float4*>(&g_part[p][off]);
                s.x += v.x; s.y += v.y; s.z += v.z; s.w += v.w;
            }
            float4 b = *reinterpret_cast<const float4*>(bias + n0 + nc4);
            float4 r;
            r.x = __half2float(__float2half_rn(__half2float(__float2half_rn(s.x)) + b.x));
            r.y = __half2float(__float2half_rn(__half2float(__float2half_rn(s.y)) + b.y));
            r.z = __half2float(__float2half_rn(__half2float(__float2half_rn(s.z)) + b.z));
            r.w = __half2float(__float2half_rn(__half2float(__float2half_rn(s.w)) + b.w));
            *reinterpret_cast<float4*>(out + off) = r;
        }
    }
}

extern "C" void kernel_launch(void* const* d_in, const int* in_sizes, int n_in,
                              void* d_out, int out_size) {
    const float* x       = (const float*)d_in[0];
    const int*   qweight = (const int*)d_in[1];
    const int*   qzeros  = (const int*)d_in[2];
    const float* scales  = (const float*)d_in[3];
    const int*   g_idx   = (const int*)d_in[4];
    const float* bias    = (const float*)d_in[5];
    float*       out     = (float*)d_out;

    const int K = in_sizes[4];      // g_idx length
    const int M = in_sizes[0] / K;  // 64
    const int N = in_sizes[5];      // 8192

    const int smem_bytes =
        (2 * 64 * LDS_A + 2 * BN * LDS_B) * (int)sizeof(__half);  // 55296
    cudaFuncSetAttribute(gptq_wmma_kernel,
                         cudaFuncAttributeMaxDynamicSharedMemorySize,
                         smem_bytes);

    const int nx = M * K;
    convert_x_kernel<<<(nx / 16 + THREADS - 1) / THREADS, THREADS>>>(x, nx);

    dim3 grid(N / BN, SPLIT);
    gptq_wmma_kernel<<<grid, THREADS, smem_bytes>>>(qweight, qzeros, scales,
                                                    g_idx, bias, out, M, K, N);
}

// round 17
// speedup vs baseline: 1.1711x; 1.0795x over previous
#include <cuda_runtime.h>
#include <cuda_fp16.h>
#include <mma.h>

using namespace nvcuda;

// GPTQ int4 dequant + GEMM: wmma, split-K, fused last-CTA reduction.
// R16: wave shaping. Grid was 64x16=1024 CTAs over 148x4=592 slots = 1.73
// waves (~15% tail idle, measured occ 39.6% < 50% theoretical). Now SPLIT=9
// with non-uniform chunk ranges -> 64x9=576 CTAs = exactly one wave.
// Static chunk assignment keeps partial grouping deterministic.
// Inputs fp16-valued f32 (harness upcasts): x:[M,K], scales:[G,N], bias:[N],
// out:[M,N] f32; qweight:[K/8,N] i32, qzeros:[G,N/8] i32, g_idx:[K] i32.

#define THREADS 256
#define BK 64
#define BN 128
#define SPLIT 9
#define MAX_M 64
#define LDS_A 72   // 144B stride: 16x9 bytes -> cp.async-aligned + LDSM-clean
#define LDS_B 72

__device__ __half g_xh[MAX_M * 8192];            // 1 MB fp16 x (k-interleaved)
__device__ float  g_part[SPLIT][MAX_M * 8192];   // fp32 partials (18 MB)
__device__ unsigned g_cnt[64];                   // per-n-tile retire counters

// x scratch holds each 8-k block in order [0,4,1,5,2,6,3,7]
__global__ void convert_x_kernel(const float* __restrict__ x, int n) {
    int i = (blockIdx.x * blockDim.x + threadIdx.x) * 16;
    if (i >= n) return;
#pragma unroll
    for (int u = 0; u < 2; ++u) {  // two 8-blocks
        const int b = i + u * 8;
        float4 v0 = *reinterpret_cast<const float4*>(x + b);      // k 0-3
        float4 v1 = *reinterpret_cast<const float4*>(x + b + 4);  // k 4-7
        *reinterpret_cast<__half2*>(g_xh + b)     = __floats2half2_rn(v0.x, v1.x);
        *reinterpret_cast<__half2*>(g_xh + b + 2) = __floats2half2_rn(v0.y, v1.y);
        *reinterpret_cast<__half2*>(g_xh + b + 4) = __floats2half2_rn(v0.z, v1.z);
        *reinterpret_cast<__half2*>(g_xh + b + 6) = __floats2half2_rn(v0.w, v1.w);
    }
}

// one LOP3 pair-extract (k-interleaved); exact hsub2 + one hmul2 == ref fp16 W
__device__ __forceinline__ unsigned dq_ilv(unsigned p, __half2 hz2, __half2 hs2) {
    unsigned t = (p & 0x000F000Fu) | 0x64006400u;
    __half2 v = __hmul2(__hsub2(*reinterpret_cast<__half2*>(&t), hz2), hs2);
    return *reinterpret_cast<unsigned*>(&v);
}

__device__ __forceinline__ void cp_async16(void* smem_dst, const void* src) {
    unsigned s = (unsigned)__cvta_generic_to_shared(smem_dst);
    asm volatile("cp.async.cg.shared.global [%0], [%1], 16;\n"
                 :: "r"(s), "l"(src));
}

__global__ __launch_bounds__(THREADS, 4) void gptq_wmma_kernel(
    const int* __restrict__ qweight, const int* __restrict__ qzeros,
    const float* __restrict__ scales, const int* __restrict__ g_idx,
    const float* __restrict__ bias, float* __restrict__ out,
    int M, int K, int N)
{
    extern __shared__ __align__(16) __half sm[];
    __half* Ab = sm;                       // [buf][row][col], ld 72
    __half* Bb = sm + 2 * 64 * LDS_A;      // [buf][n][k], ld 72

    const int tid  = threadIdx.x;
    const int n0   = blockIdx.x * BN;
    const int spl  = blockIdx.y;
    // non-uniform split: chunk range [c0, c1) of K/BK total chunks
    const int nchT = K / BK;                       // 128
    const int c0   = (spl * nchT) / SPLIT;
    const int c1   = ((spl + 1) * nchT) / SPLIT;
    const int kbeg = c0 * BK;
    const int kend = c1 * BK;

    // dequant mapping: thread owns column bn; qweight krows kq+2u (u=0..3)
    const int bn   = tid & 127;
    const int kq   = tid >> 7;  // 0..1
    const int gn   = n0 + bn;
    const int zcol = gn >> 3;
    const int zsh  = (gn & 7) * 4;
    const int Nz   = N >> 3;

    // warp tiling: 8 warps -> (2 m32) x (4 n32)
    const int wid = tid >> 5;
    const int mr  = wid & 1;
    const int ng  = wid >> 1;

    unsigned qReg[4];
    __half2  hz2 = __half2half2(__ushort_as_half(0x6400));
    __half2  hs2 = __half2half2(__ushort_as_half(0));

    // A: cp.async direct gmem(g_xh, L2-resident) -> SMEM; 512 x 16B segs
    auto issue_A = [&](int k0, int buf) {
        __half* A = Ab + buf * 64 * LDS_A;
#pragma unroll
        for (int u = 0; u < 2; ++u) {
            const int i = tid + u * THREADS;       // 0..511
            const int row = i >> 3, seg = i & 7;   // 64 rows x 8 segs
            if (row < M)
                cp_async16(A + row * LDS_A + seg * 8,
                           g_xh + (size_t)row * K + k0 + seg * 8);
        }
        asm volatile("cp.async.commit_group;\n");
    };

    auto load_q = [&](int k0) {
        const int krow = k0 >> 3;
#pragma unroll
        for (int u = 0; u < 4; ++u)
            qReg[u] = (unsigned)qweight[(size_t)(krow + kq + 2 * u) * N + gn];
        const int g = g_idx[k0];  // uniform across 64-chunk (groupsize 128)
        const unsigned zq = (unsigned)qzeros[(size_t)g * Nz + zcol];
        const int z = (int)((zq >> zsh) & 15u) + 1;
        hz2 = __half2half2(__ushort_as_half((unsigned short)(0x6400 + z)));
        hs2 = __half2half2(__float2half_rn(scales[(size_t)g * N + gn]));
    };

    auto stage_B = [&](int buf) {
        __half* B = Bb + buf * 128 * LDS_B;
#pragma unroll
        for (int u = 0; u < 4; ++u) {
            const unsigned q = qReg[u];
            // interleaved dequant: positions [0..7] hold k [0,4,1,5,2,6,3,7]
            uint4 v;
            v.x = dq_ilv(q,       hz2, hs2);
            v.y = dq_ilv(q >> 4,  hz2, hs2);
            v.z = dq_ilv(q >> 8,  hz2, hs2);
            v.w = dq_ilv(q >> 12, hz2, hs2);
            *reinterpret_cast<uint4*>(B + bn * LDS_B + (kq + 2 * u) * 8) = v;
        }
    };

    // zero A pad rows once (rows >= M are never written by cp.async)
    if (M < 64) {
        for (int i = tid; i < 2 * (64 - M) * 8; i += THREADS) {
            const int b = i / ((64 - M) * 8);
            const int r = M + (i / 8) % (64 - M);
            const int s = i & 7;
            *reinterpret_cast<uint4*>(Ab + b * 64 * LDS_A + r * LDS_A + s * 8) =
                make_uint4(0u, 0u, 0u, 0u);
        }
        __syncthreads();
    }

    wmma::fragment<wmma::accumulator, 16, 16, 16, float> c[2][2];
#pragma unroll
    for (int im = 0; im < 2; ++im)
#pragma unroll
        for (int in = 0; in < 2; ++in)
            wmma::fill_fragment(c[im][in], 0.f);

    issue_A(kbeg, 0);
    load_q(kbeg);
    int buf = 0;
    for (int k0 = kbeg; k0 < kend; k0 += BK) {
        stage_B(buf);
        asm volatile("cp.async.wait_group 0;\n" ::: "memory");
        __syncthreads();
        if (k0 + BK < kend) {
            issue_A(k0 + BK, buf ^ 1);  // buf^1 retired by barrier above
            load_q(k0 + BK);            // overlaps mma below
        }
        const __half* A = Ab + buf * 64 * LDS_A;
        const __half* B = Bb + buf * 128 * LDS_B;
#pragma unroll
        for (int ks = 0; ks < BK / 16; ++ks) {
            wmma::fragment<wmma::matrix_a, 16, 16, 16, __half, wmma::row_major> a[2];
#pragma unroll
            for (int im = 0; im < 2; ++im)
                wmma::load_matrix_sync(
                    a[im], A + (mr * 32 + im * 16) * LDS_A + ks * 16, LDS_A);
#pragma unroll
            for (int in = 0; in < 2; ++in) {
                wmma::fragment<wmma::matrix_b, 16, 16, 16, __half, wmma::col_major> b;
                wmma::load_matrix_sync(
                    b, B + (ng * 32 + in * 16) * LDS_B + ks * 16, LDS_B);
#pragma unroll
                for (int im = 0; im < 2; ++im)
                    wmma::mma_sync(c[im][in], a[im], b, c[im][in]);
            }
        }
        buf ^= 1;
        // single barrier per chunk: writes at iter i+1 target buf^1, whose last
        // readers (mma at i-1) are ordered by the barrier at iter i.
    }

    // ---- store fp32 partial tile
    float* dst = g_part[spl];
#pragma unroll
    for (int im = 0; im < 2; ++im)
#pragma unroll
        for (int in = 0; in < 2; ++in)
            wmma::store_matrix_sync(
                dst + (size_t)(mr * 32 + im * 16) * N + n0 + ng * 32 + in * 16,
                c[im][in], N, wmma::mem_row_major);

    // ---- last CTA per n-tile reduces (threadFenceReduction pattern)
    __shared__ bool isLast;
    __threadfence();
    __syncthreads();
    if (tid == 0) {
        unsigned old = atomicInc(&g_cnt[blockIdx.x], SPLIT - 1);  // self-resets
        isLast = (old == SPLIT - 1);
    }
    __syncthreads();

    if (isLast) {
        __threadfence();  // acquire: see all peers' partial stores
#pragma unroll
        for (int u = 0; u < 8; ++u) {
            const int i   = tid + u * THREADS;   // 0..2047 float4 slots
            const int row = i >> 5;              // 0..63
            const int nc4 = (i & 31) * 4;        // 0..124
            if (row >= M) continue;
            const size_t off = (size_t)row * N + n0 + nc4;
            float4 s = make_float4(0.f, 0.f, 0.f, 0.f);
#pragma unroll
            for (int p = 0; p < SPLIT; ++p) {
                float4 v = *reinterpret_cast<const float4*>(&g_part[p][off]);
                s.x += v.x; s.y += v.y; s.z += v.z; s.w += v.w;
            }
            float4 b = *reinterpret_cast<const float4*>(bias + n0 + nc4);
            float4 r;
            r.x = __half2float(__float2half_rn(__half2float(__float2half_rn(s.x)) + b.x));
            r.y = __half2float(__float2half_rn(__half2float(__float2half_rn(s.y)) + b.y));
            r.z = __half2float(__float2half_rn(__half2float(__float2half_rn(s.z)) + b.z));
            r.w = __half2float(__float2half_rn(__half2float(__float2half_rn(s.w)) + b.w));
            *reinterpret_cast<float4*>(out + off) = r;
        }
    }
}

extern "C" void kernel_launch(void* const* d_in, const int* in_sizes, int n_in,
                              void* d_out, int out_size) {
    const float* x       = (const float*)d_in[0];
    const int*   qweight = (const int*)d_in[1];
    const int*   qzeros  = (const int*)d_in[2];
    const float* scales  = (const float*)d_in[3];
    const int*   g_idx   = (const int*)d_in[4];
    const float* bias    = (const float*)d_in[5];
    float*       out     = (float*)d_out;

    const int K = in_sizes[4];      // g_idx length
    const int M = in_sizes[0] / K;  // 64
    const int N = in_sizes[5];      // 8192

    const int smem_bytes =
        (2 * 64 * LDS_A + 2 * BN * LDS_B) * (int)sizeof(__half);  // 55296
    cudaFuncSetAttribute(gptq_wmma_kernel,
                         cudaFuncAttributeMaxDynamicSharedMemorySize,
                         smem_bytes);

    const int nx = M * K;
    convert_x_kernel<<<(nx / 16 + THREADS - 1) / THREADS, THREADS>>>(x, nx);

    dim3 grid(N / BN, SPLIT);
    gptq_wmma_kernel<<<grid, THREADS, smem_bytes>>>(qweight, qzeros, scales,
                                                    g_idx, bias, out, M, K, N);
}